// round 4
// baseline (speedup 1.0000x reference)
#include <cuda_runtime.h>

#define BATCH 4
#define SEQ   4096
#define NEMB  1024
#define HD    128
#define BM    64
#define BN    64
#define PBK   32

// Scratch (device globals: allocation-free per harness rules)
__device__ float g_q[BATCH * SEQ * HD];
__device__ float g_k[BATCH * SEQ * HD];
__device__ float g_v[BATCH * SEQ * HD];

// ---------------------------------------------------------------------------
// QKV projection: out[m][n] = sum_k x[m][k] * W[k][n];  M=16384, K=1024, N=128
// grid = (M/BM, 3)  (z selects Wq/Wk/Wv), 256 threads, 4x8 micro-tile
// ---------------------------------------------------------------------------
__global__ __launch_bounds__(256, 2) void proj_kernel(
    const float* __restrict__ x,
    const float* __restrict__ Wq,
    const float* __restrict__ Wk,
    const float* __restrict__ Wv)
{
    __shared__ float xs[BM][PBK + 4];    // stride 36 floats (16B-aligned rows)
    __shared__ float ws[PBK][HD + 4];    // stride 132 floats

    const int which = blockIdx.y;
    const float* __restrict__ Wp = (which == 0) ? Wq : (which == 1) ? Wk : Wv;
    float* __restrict__ outp     = (which == 0) ? g_q : (which == 1) ? g_k : g_v;

    const int m0  = blockIdx.x * BM;
    const int tid = threadIdx.x;
    const int tx  = tid & 15, ty = tid >> 4;

    float acc[4][8];
#pragma unroll
    for (int i = 0; i < 4; i++)
#pragma unroll
        for (int j = 0; j < 8; j++) acc[i][j] = 0.f;

    for (int k0 = 0; k0 < NEMB; k0 += PBK) {
        // x tile 64x32 = 512 float4
#pragma unroll
        for (int i = 0; i < 2; i++) {
            int idx = tid + i * 256;
            int r = idx >> 3, c4 = idx & 7;
            float4 v = *reinterpret_cast<const float4*>(x + (size_t)(m0 + r) * NEMB + k0 + c4 * 4);
            *reinterpret_cast<float4*>(&xs[r][c4 * 4]) = v;
        }
        // W tile 32x128 = 1024 float4
#pragma unroll
        for (int i = 0; i < 4; i++) {
            int idx = tid + i * 256;
            int r = idx >> 5, c4 = idx & 31;
            float4 v = *reinterpret_cast<const float4*>(Wp + (size_t)(k0 + r) * HD + c4 * 4);
            *reinterpret_cast<float4*>(&ws[r][c4 * 4]) = v;
        }
        __syncthreads();

#pragma unroll 8
        for (int kk = 0; kk < PBK; kk++) {
            int kkp = (kk + tx) & (PBK - 1);   // per-thread rotation: bank spread
            float a[4];
#pragma unroll
            for (int i = 0; i < 4; i++) a[i] = xs[ty * 4 + i][kkp];
            float4 b0 = *reinterpret_cast<const float4*>(&ws[kkp][tx * 8]);
            float4 b1 = *reinterpret_cast<const float4*>(&ws[kkp][tx * 8 + 4]);
            float b[8] = {b0.x, b0.y, b0.z, b0.w, b1.x, b1.y, b1.z, b1.w};
#pragma unroll
            for (int i = 0; i < 4; i++)
#pragma unroll
                for (int j = 0; j < 8; j++) acc[i][j] += a[i] * b[j];
        }
        __syncthreads();
    }

#pragma unroll
    for (int i = 0; i < 4; i++) {
        size_t r = (size_t)(m0 + ty * 4 + i);
#pragma unroll
        for (int j = 0; j < 8; j += 4) {
            float4 v = make_float4(acc[i][j], acc[i][j + 1], acc[i][j + 2], acc[i][j + 3]);
            *reinterpret_cast<float4*>(outp + r * HD + tx * 8 + j) = v;
        }
    }
}

// ---------------------------------------------------------------------------
// Flash attention, causal. BM=BN=64, H=128, 256 threads (16x16).
// K and V share one smem buffer (V loaded after S).  exp2-domain softmax.
// ---------------------------------------------------------------------------
#define QS_STRIDE 132
#define PS_STRIDE 65
#define Q_OFF  0
#define KV_OFF (BM * QS_STRIDE)
#define P_OFF  (2 * BM * QS_STRIDE)
#define ATTN_SMEM_FLOATS (2 * BM * QS_STRIDE + BM * PS_STRIDE)
#define ATTN_SMEM_BYTES  (ATTN_SMEM_FLOATS * 4)

__global__ __launch_bounds__(256, 2) void attn_kernel(float* __restrict__ out)
{
    extern __shared__ float sm[];
    float* Qs  = sm + Q_OFF;    // [64][132]
    float* KVs = sm + KV_OFF;   // [64][132]
    float* Ps  = sm + P_OFF;    // [64][65]

    const int b  = blockIdx.y;
    const int bx = blockIdx.x;
    // heavy/light pairing against causal skew
    const int ib = (bx & 1) ? (SEQ / BM - 1 - (bx >> 1)) : (bx >> 1);
    const int q0 = ib * BM;
    const int tid = threadIdx.x;
    const int tx = tid & 15, ty = tid >> 4;

    const float sc = 0.03125f * 1.44269504088896340736f; // (1/sqrt(1024)) * log2(e)

    const float* __restrict__ qg = g_q + ((size_t)b * SEQ + q0) * HD;
#pragma unroll
    for (int i = 0; i < 8; i++) {
        int idx = tid + i * 256;
        int r = idx >> 5, c4 = idx & 31;
        float4 v = *reinterpret_cast<const float4*>(qg + (size_t)r * HD + c4 * 4);
        v.x *= sc; v.y *= sc; v.z *= sc; v.w *= sc;
        *reinterpret_cast<float4*>(Qs + r * QS_STRIDE + c4 * 4) = v;
    }

    float o[4][8], m[4], l[4];
#pragma unroll
    for (int i = 0; i < 4; i++) {
        m[i] = -1e30f; l[i] = 0.f;
#pragma unroll
        for (int j = 0; j < 8; j++) o[i][j] = 0.f;
    }

    for (int jb = 0; jb <= ib; jb++) {
        __syncthreads();  // Qs ready (first iter) / prev V reads done
        const float* __restrict__ kg = g_k + ((size_t)b * SEQ + (size_t)jb * BN) * HD;
#pragma unroll
        for (int i = 0; i < 8; i++) {
            int idx = tid + i * 256;
            int r = idx >> 5, c4 = idx & 31;
            *reinterpret_cast<float4*>(KVs + r * QS_STRIDE + c4 * 4) =
                *reinterpret_cast<const float4*>(kg + (size_t)r * HD + c4 * 4);
        }
        __syncthreads();

        // ---- S = Q * K^T (4x4 per thread), per-thread kk rotation ----
        float s[4][4];
#pragma unroll
        for (int i = 0; i < 4; i++)
#pragma unroll
            for (int j = 0; j < 4; j++) s[i][j] = 0.f;

        const float* qr = Qs  + (ty * 4) * QS_STRIDE;
        const float* kr = KVs + (tx * 4) * QS_STRIDE;
#pragma unroll 8
        for (int kk = 0; kk < HD; kk++) {
            int kkp = (kk + 2 * tx) & (HD - 1);
            float a0 = qr[kkp];
            float a1 = qr[QS_STRIDE + kkp];
            float a2 = qr[2 * QS_STRIDE + kkp];
            float a3 = qr[3 * QS_STRIDE + kkp];
            float c0 = kr[kkp];
            float c1 = kr[QS_STRIDE + kkp];
            float c2 = kr[2 * QS_STRIDE + kkp];
            float c3 = kr[3 * QS_STRIDE + kkp];
            s[0][0] += a0 * c0; s[0][1] += a0 * c1; s[0][2] += a0 * c2; s[0][3] += a0 * c3;
            s[1][0] += a1 * c0; s[1][1] += a1 * c1; s[1][2] += a1 * c2; s[1][3] += a1 * c3;
            s[2][0] += a2 * c0; s[2][1] += a2 * c1; s[2][2] += a2 * c2; s[2][3] += a2 * c3;
            s[3][0] += a3 * c0; s[3][1] += a3 * c1; s[3][2] += a3 * c2; s[3][3] += a3 * c3;
        }

        if (jb == ib) {
#pragma unroll
            for (int i = 0; i < 4; i++) {
                int r = ty * 4 + i;
#pragma unroll
                for (int j = 0; j < 4; j++)
                    if (tx * 4 + j > r) s[i][j] = -1e30f;
            }
        }

        // ---- online softmax (row reduce over 16 tx threads) ----
#pragma unroll
        for (int i = 0; i < 4; i++) {
            float mx = fmaxf(fmaxf(s[i][0], s[i][1]), fmaxf(s[i][2], s[i][3]));
#pragma unroll
            for (int w = 8; w >= 1; w >>= 1)
                mx = fmaxf(mx, __shfl_xor_sync(0xffffffffu, mx, w, 16));
            float mnew  = fmaxf(m[i], mx);
            float alpha = exp2f(m[i] - mnew);
            m[i] = mnew;
            float ls = 0.f;
#pragma unroll
            for (int j = 0; j < 4; j++) {
                float p = exp2f(s[i][j] - mnew);
                s[i][j] = p;
                ls += p;
            }
#pragma unroll
            for (int w = 8; w >= 1; w >>= 1)
                ls += __shfl_xor_sync(0xffffffffu, ls, w, 16);
            l[i] = l[i] * alpha + ls;
#pragma unroll
            for (int j = 0; j < 8; j++) o[i][j] *= alpha;
#pragma unroll
            for (int j = 0; j < 4; j++)
                Ps[(ty * 4 + i) * PS_STRIDE + tx * 4 + j] = s[i][j];
        }
        __syncthreads();  // Ps visible; K reads done -> safe to overwrite KVs

        const float* __restrict__ vg = g_v + ((size_t)b * SEQ + (size_t)jb * BN) * HD;
#pragma unroll
        for (int i = 0; i < 8; i++) {
            int idx = tid + i * 256;
            int r = idx >> 5, c4 = idx & 31;
            *reinterpret_cast<float4*>(KVs + r * QS_STRIDE + c4 * 4) =
                *reinterpret_cast<const float4*>(vg + (size_t)r * HD + c4 * 4);
        }
        __syncthreads();

        // ---- O += P * V (4x8 per thread), per-thread kk rotation ----
        const float* pr = Ps + (ty * 4) * PS_STRIDE;
#pragma unroll 4
        for (int kk = 0; kk < BN; kk++) {
            int kkp = (kk + tx) & (BN - 1);
            float p0 = pr[kkp];
            float p1 = pr[PS_STRIDE + kkp];
            float p2 = pr[2 * PS_STRIDE + kkp];
            float p3 = pr[3 * PS_STRIDE + kkp];
            float4 v0 = *reinterpret_cast<const float4*>(KVs + kkp * QS_STRIDE + tx * 8);
            float4 v1 = *reinterpret_cast<const float4*>(KVs + kkp * QS_STRIDE + tx * 8 + 4);
            float vv[8] = {v0.x, v0.y, v0.z, v0.w, v1.x, v1.y, v1.z, v1.w};
#pragma unroll
            for (int j = 0; j < 8; j++) {
                o[0][j] += p0 * vv[j];
                o[1][j] += p1 * vv[j];
                o[2][j] += p2 * vv[j];
                o[3][j] += p3 * vv[j];
            }
        }
    }

    // ---- epilogue: O /= l ----
    float* __restrict__ og = out + ((size_t)b * SEQ + q0) * HD;
#pragma unroll
    for (int i = 0; i < 4; i++) {
        float inv = 1.f / l[i];
        size_t r = (size_t)(ty * 4 + i);
#pragma unroll
        for (int j = 0; j < 8; j += 4) {
            float4 v = make_float4(o[i][j] * inv, o[i][j + 1] * inv,
                                   o[i][j + 2] * inv, o[i][j + 3] * inv);
            *reinterpret_cast<float4*>(og + r * HD + tx * 8 + j) = v;
        }
    }
}

// ---------------------------------------------------------------------------
extern "C" void kernel_launch(void* const* d_in, const int* in_sizes, int n_in,
                              void* d_out, int out_size)
{
    const float* x  = (const float*)d_in[0];
    const float* Wq = (const float*)d_in[1];
    const float* Wk = (const float*)d_in[2];
    const float* Wv = (const float*)d_in[3];
    float* out = (float*)d_out;

    cudaFuncSetAttribute(attn_kernel, cudaFuncAttributeMaxDynamicSharedMemorySize,
                         ATTN_SMEM_BYTES);

    dim3 pg((BATCH * SEQ) / BM, 3);
    proj_kernel<<<pg, 256>>>(x, Wq, Wk, Wv);

    dim3 ag(SEQ / BM, BATCH);
    attn_kernel<<<ag, 256, ATTN_SMEM_BYTES>>>(out);
}

// round 5
// speedup vs baseline: 3.1216x; 3.1216x over previous
#include <cuda_runtime.h>
#include <cstdint>

#define BATCH 4
#define SEQ   4096
#define NEMB  1024
#define HD    128

__device__ float g_q[BATCH * SEQ * HD];
__device__ float g_k[BATCH * SEQ * HD];
__device__ float g_v[BATCH * SEQ * HD];

__device__ __forceinline__ float f2tf_f(float x) {
    uint32_t r;
    asm("cvt.rna.tf32.f32 %0, %1;" : "=r"(r) : "f"(x));
    return __uint_as_float(r);
}
__device__ __forceinline__ float ex2(float x) {
    float r;
    asm("ex2.approx.f32 %0, %1;" : "=f"(r) : "f"(x));
    return r;
}
__device__ __forceinline__ void mma8(float* d, const uint32_t* a, uint32_t b0, uint32_t b1) {
    asm volatile(
        "mma.sync.aligned.m16n8k8.row.col.f32.tf32.tf32.f32 "
        "{%0,%1,%2,%3}, {%4,%5,%6,%7}, {%8,%9}, {%0,%1,%2,%3};"
        : "+f"(d[0]), "+f"(d[1]), "+f"(d[2]), "+f"(d[3])
        : "r"(a[0]), "r"(a[1]), "r"(a[2]), "r"(a[3]), "r"(b0), "r"(b1));
}

// ---------------------------------------------------------------------------
// QKV projection, split-tf32 hi/lo. out[m][n] = sum_k x[m][k]*W[k][n]
// Block: 128x128 tile, 8 warps (4 wm x 2 wn), BK=16.
// ---------------------------------------------------------------------------
#define P_LD 20
__global__ __launch_bounds__(256, 2) void proj_kernel(
    const float* __restrict__ x,
    const float* __restrict__ Wq,
    const float* __restrict__ Wk,
    const float* __restrict__ Wv)
{
    __shared__ float Ah[128][P_LD], Al[128][P_LD];
    __shared__ float Bh[128][P_LD], Bl[128][P_LD];   // W transposed: [n][k]

    const int which = blockIdx.y;
    const float* __restrict__ W = (which == 0) ? Wq : (which == 1) ? Wk : Wv;
    float* __restrict__ outp    = (which == 0) ? g_q : (which == 1) ? g_k : g_v;

    const int m0   = blockIdx.x * 128;
    const int tid  = threadIdx.x;
    const int lane = tid & 31, wid = tid >> 5;
    const int wm = wid & 3, wn = wid >> 2;
    const int qr = lane >> 2, qc = lane & 3;

    float acc[2][8][4];
#pragma unroll
    for (int mt = 0; mt < 2; mt++)
#pragma unroll
        for (int nt = 0; nt < 8; nt++)
#pragma unroll
            for (int e = 0; e < 4; e++) acc[mt][nt][e] = 0.f;

    for (int k0 = 0; k0 < NEMB; k0 += 16) {
#pragma unroll
        for (int i = 0; i < 2; i++) {           // x tile 128x16
            int idx = tid + i * 256;
            int r = idx >> 2, c4 = idx & 3;
            float4 v = *reinterpret_cast<const float4*>(x + (size_t)(m0 + r) * NEMB + k0 + c4 * 4);
            float4 h, l;
            h.x = f2tf_f(v.x); l.x = f2tf_f(v.x - h.x);
            h.y = f2tf_f(v.y); l.y = f2tf_f(v.y - h.y);
            h.z = f2tf_f(v.z); l.z = f2tf_f(v.z - h.z);
            h.w = f2tf_f(v.w); l.w = f2tf_f(v.w - h.w);
            *reinterpret_cast<float4*>(&Ah[r][c4 * 4]) = h;
            *reinterpret_cast<float4*>(&Al[r][c4 * 4]) = l;
        }
#pragma unroll
        for (int rr = 0; rr < 8; rr++) {        // W tile 16x128 -> transposed
            int p  = wid + 8 * rr;
            int kk = (p & 3) * 4 + (lane >> 3);
            int nn = (p >> 2) * 8 + (lane & 7);
            float v = W[(size_t)(k0 + kk) * HD + nn];
            float h = f2tf_f(v);
            Bh[nn][kk] = h;
            Bl[nn][kk] = f2tf_f(v - h);
        }
        __syncthreads();

#pragma unroll
        for (int ks = 0; ks < 2; ks++) {
            uint32_t ahi[2][4], alo[2][4];
            int c0 = ks * 8 + qc;
#pragma unroll
            for (int mt = 0; mt < 2; mt++) {
                int r0 = wm * 32 + mt * 16 + qr;
                ahi[mt][0] = __float_as_uint(Ah[r0][c0]);
                ahi[mt][1] = __float_as_uint(Ah[r0 + 8][c0]);
                ahi[mt][2] = __float_as_uint(Ah[r0][c0 + 4]);
                ahi[mt][3] = __float_as_uint(Ah[r0 + 8][c0 + 4]);
                alo[mt][0] = __float_as_uint(Al[r0][c0]);
                alo[mt][1] = __float_as_uint(Al[r0 + 8][c0]);
                alo[mt][2] = __float_as_uint(Al[r0][c0 + 4]);
                alo[mt][3] = __float_as_uint(Al[r0 + 8][c0 + 4]);
            }
#pragma unroll
            for (int nt = 0; nt < 8; nt++) {
                int n0 = wn * 64 + nt * 8 + qr;
                uint32_t bh0 = __float_as_uint(Bh[n0][c0]);
                uint32_t bh1 = __float_as_uint(Bh[n0][c0 + 4]);
                uint32_t bl0 = __float_as_uint(Bl[n0][c0]);
                uint32_t bl1 = __float_as_uint(Bl[n0][c0 + 4]);
#pragma unroll
                for (int mt = 0; mt < 2; mt++) {
                    mma8(acc[mt][nt], ahi[mt], bh0, bh1);
                    mma8(acc[mt][nt], ahi[mt], bl0, bl1);
                    mma8(acc[mt][nt], alo[mt], bh0, bh1);
                }
            }
        }
        __syncthreads();
    }

#pragma unroll
    for (int mt = 0; mt < 2; mt++)
#pragma unroll
        for (int nt = 0; nt < 8; nt++) {
            int row = m0 + wm * 32 + mt * 16 + qr;
            int col = wn * 64 + nt * 8 + 2 * qc;
            *reinterpret_cast<float2*>(outp + (size_t)row * HD + col) =
                make_float2(acc[mt][nt][0], acc[mt][nt][1]);
            *reinterpret_cast<float2*>(outp + (size_t)(row + 8) * HD + col) =
                make_float2(acc[mt][nt][2], acc[mt][nt][3]);
        }
}

// ---------------------------------------------------------------------------
// Flash attention, causal, tf32 mma. BM=BN=64, 128 threads, warp owns 16 rows.
// Smem: Qs[64][132] (P-scratch aliases here after frag extraction),
//       Ks[64][132], Vs[64][136].  Total 100 KB -> 2 blocks/SM.
// ---------------------------------------------------------------------------
#define QK_LD 132
#define V_LD  136
#define PS_LD 68
#define K_OFF  (64 * QK_LD)
#define V_OFF  (2 * 64 * QK_LD)
#define ATTN_SMEM_FLOATS (2 * 64 * QK_LD + 64 * V_LD)
#define ATTN_SMEM_BYTES  (ATTN_SMEM_FLOATS * 4)

__global__ __launch_bounds__(128) void attn_kernel(float* __restrict__ out)
{
    extern __shared__ float sm[];
    float* Qs = sm;
    float* Ks = sm + K_OFF;
    float* Vs = sm + V_OFF;

    const int b  = blockIdx.y;
    const int bx = blockIdx.x;
    const int ib = (bx & 1) ? (SEQ / 64 - 1 - (bx >> 1)) : (bx >> 1);
    const int q0 = ib * 64;
    const int tid = threadIdx.x;
    const int lane = tid & 31, w = tid >> 5;
    const int qr = lane >> 2, qc = lane & 3;
    float* Ps = sm + w * 16 * PS_LD;   // aliases Qs (dead after frag extraction)

    const float sc = 0.03125f * 1.44269504088896340736f; // 1/sqrt(1024) * log2(e)

    // ---- Q fill (warp-private rows), frags to registers ----
    const float* __restrict__ qg = g_q + ((size_t)b * SEQ + q0) * HD;
#pragma unroll
    for (int i = 0; i < 16; i++) {
        int r = 16 * w + i;
        float4 v = *reinterpret_cast<const float4*>(qg + (size_t)r * HD + lane * 4);
        v.x = f2tf_f(v.x * sc); v.y = f2tf_f(v.y * sc);
        v.z = f2tf_f(v.z * sc); v.w = f2tf_f(v.w * sc);
        *reinterpret_cast<float4*>(Qs + r * QK_LD + lane * 4) = v;
    }
    __syncwarp();
    uint32_t qa[16][4];
    {
        const uint32_t* Qu = reinterpret_cast<const uint32_t*>(Qs);
#pragma unroll
        for (int kt = 0; kt < 16; kt++) {
            int base = (16 * w + qr) * QK_LD + kt * 8 + qc;
            qa[kt][0] = Qu[base];
            qa[kt][1] = Qu[base + 8 * QK_LD];
            qa[kt][2] = Qu[base + 4];
            qa[kt][3] = Qu[base + 8 * QK_LD + 4];
        }
    }

    float o[16][4];
#pragma unroll
    for (int nt = 0; nt < 16; nt++)
#pragma unroll
        for (int e = 0; e < 4; e++) o[nt][e] = 0.f;
    float m_lo = -1e30f, m_hi = -1e30f, l_lo = 0.f, l_hi = 0.f;

    const float* __restrict__ kg = g_k + (size_t)b * SEQ * HD;
    const float* __restrict__ vg = g_v + (size_t)b * SEQ * HD;

    for (int jb = 0; jb <= ib; jb++) {
        __syncthreads();   // Q-frag extraction done (1st) / prev Vs+Ps reads done
        // fill K and V tiles (tf32-rounded)
#pragma unroll
        for (int i = 0; i < 16; i++) {
            int idx = tid + i * 128;
            int r = idx >> 5, c4 = idx & 31;
            float4 kv = *reinterpret_cast<const float4*>(kg + ((size_t)jb * 64 + r) * HD + c4 * 4);
            kv.x = f2tf_f(kv.x); kv.y = f2tf_f(kv.y);
            kv.z = f2tf_f(kv.z); kv.w = f2tf_f(kv.w);
            *reinterpret_cast<float4*>(Ks + r * QK_LD + c4 * 4) = kv;
            float4 vv = *reinterpret_cast<const float4*>(vg + ((size_t)jb * 64 + r) * HD + c4 * 4);
            vv.x = f2tf_f(vv.x); vv.y = f2tf_f(vv.y);
            vv.z = f2tf_f(vv.z); vv.w = f2tf_f(vv.w);
            *reinterpret_cast<float4*>(Vs + r * V_LD + c4 * 4) = vv;
        }
        __syncthreads();

        // ---- S = Q * K^T : 8 n-tiles x 16 k-tiles ----
        float s[8][4];
#pragma unroll
        for (int nt = 0; nt < 8; nt++)
#pragma unroll
            for (int e = 0; e < 4; e++) s[nt][e] = 0.f;
        const uint32_t* Ku = reinterpret_cast<const uint32_t*>(Ks);
#pragma unroll
        for (int nt = 0; nt < 8; nt++) {
            int n0 = nt * 8 + qr;
#pragma unroll
            for (int kt = 0; kt < 16; kt++) {
                uint32_t b0 = Ku[n0 * QK_LD + kt * 8 + qc];
                uint32_t b1 = Ku[n0 * QK_LD + kt * 8 + qc + 4];
                mma8(s[nt], qa[kt], b0, b1);
            }
        }

        // ---- causal mask (diagonal block only) ----
        if (jb == ib) {
            int r_lo = 16 * w + qr, r_hi = r_lo + 8;
#pragma unroll
            for (int nt = 0; nt < 8; nt++) {
                int c = nt * 8 + 2 * qc;
                if (c     > r_lo) s[nt][0] = -1e30f;
                if (c + 1 > r_lo) s[nt][1] = -1e30f;
                if (c     > r_hi) s[nt][2] = -1e30f;
                if (c + 1 > r_hi) s[nt][3] = -1e30f;
            }
        }

        // ---- online softmax (rows qr and qr+8; reduce over qc quad) ----
        float mx_lo = -1e30f, mx_hi = -1e30f;
#pragma unroll
        for (int nt = 0; nt < 8; nt++) {
            mx_lo = fmaxf(mx_lo, fmaxf(s[nt][0], s[nt][1]));
            mx_hi = fmaxf(mx_hi, fmaxf(s[nt][2], s[nt][3]));
        }
#pragma unroll
        for (int d = 1; d <= 2; d <<= 1) {
            mx_lo = fmaxf(mx_lo, __shfl_xor_sync(0xffffffffu, mx_lo, d));
            mx_hi = fmaxf(mx_hi, __shfl_xor_sync(0xffffffffu, mx_hi, d));
        }
        float mn_lo = fmaxf(m_lo, mx_lo), mn_hi = fmaxf(m_hi, mx_hi);
        float al_lo = ex2(m_lo - mn_lo),  al_hi = ex2(m_hi - mn_hi);
        m_lo = mn_lo; m_hi = mn_hi;
        float ls_lo = 0.f, ls_hi = 0.f;
#pragma unroll
        for (int nt = 0; nt < 8; nt++) {
            s[nt][0] = ex2(s[nt][0] - mn_lo);
            s[nt][1] = ex2(s[nt][1] - mn_lo);
            s[nt][2] = ex2(s[nt][2] - mn_hi);
            s[nt][3] = ex2(s[nt][3] - mn_hi);
            ls_lo += s[nt][0] + s[nt][1];
            ls_hi += s[nt][2] + s[nt][3];
        }
#pragma unroll
        for (int d = 1; d <= 2; d <<= 1) {
            ls_lo += __shfl_xor_sync(0xffffffffu, ls_lo, d);
            ls_hi += __shfl_xor_sync(0xffffffffu, ls_hi, d);
        }
        l_lo = l_lo * al_lo + ls_lo;
        l_hi = l_hi * al_hi + ls_hi;
#pragma unroll
        for (int nt = 0; nt < 16; nt++) {
            o[nt][0] *= al_lo; o[nt][1] *= al_lo;
            o[nt][2] *= al_hi; o[nt][3] *= al_hi;
        }

        // ---- P -> per-warp smem (tf32-rounded), then PV ----
#pragma unroll
        for (int nt = 0; nt < 8; nt++) {
            *reinterpret_cast<float2*>(Ps + qr * PS_LD + nt * 8 + 2 * qc) =
                make_float2(f2tf_f(s[nt][0]), f2tf_f(s[nt][1]));
            *reinterpret_cast<float2*>(Ps + (qr + 8) * PS_LD + nt * 8 + 2 * qc) =
                make_float2(f2tf_f(s[nt][2]), f2tf_f(s[nt][3]));
        }
        __syncwarp();

        const uint32_t* Pu = reinterpret_cast<const uint32_t*>(Ps);
        const uint32_t* Vu = reinterpret_cast<const uint32_t*>(Vs);
#pragma unroll
        for (int kt = 0; kt < 8; kt++) {
            uint32_t pa[4];
            pa[0] = Pu[qr * PS_LD + kt * 8 + qc];
            pa[1] = Pu[(qr + 8) * PS_LD + kt * 8 + qc];
            pa[2] = Pu[qr * PS_LD + kt * 8 + qc + 4];
            pa[3] = Pu[(qr + 8) * PS_LD + kt * 8 + qc + 4];
#pragma unroll
            for (int nt = 0; nt < 16; nt++) {
                int n0 = nt * 8 + qr;
                uint32_t b0 = Vu[(kt * 8 + qc) * V_LD + n0];
                uint32_t b1 = Vu[(kt * 8 + qc + 4) * V_LD + n0];
                mma8(o[nt], pa, b0, b1);
            }
        }
    }

    // ---- epilogue ----
    float inv_lo = 1.f / l_lo, inv_hi = 1.f / l_hi;
    float* __restrict__ og = out + ((size_t)b * SEQ + q0) * HD;
    int r_lo = 16 * w + qr;
#pragma unroll
    for (int nt = 0; nt < 16; nt++) {
        int col = nt * 8 + 2 * qc;
        *reinterpret_cast<float2*>(og + (size_t)r_lo * HD + col) =
            make_float2(o[nt][0] * inv_lo, o[nt][1] * inv_lo);
        *reinterpret_cast<float2*>(og + (size_t)(r_lo + 8) * HD + col) =
            make_float2(o[nt][2] * inv_hi, o[nt][3] * inv_hi);
    }
}

// ---------------------------------------------------------------------------
extern "C" void kernel_launch(void* const* d_in, const int* in_sizes, int n_in,
                              void* d_out, int out_size)
{
    const float* x  = (const float*)d_in[0];
    const float* Wq = (const float*)d_in[1];
    const float* Wk = (const float*)d_in[2];
    const float* Wv = (const float*)d_in[3];
    float* out = (float*)d_out;

    cudaFuncSetAttribute(attn_kernel, cudaFuncAttributeMaxDynamicSharedMemorySize,
                         ATTN_SMEM_BYTES);

    dim3 pg(128, 3);
    proj_kernel<<<pg, 256>>>(x, Wq, Wk, Wv);

    dim3 ag(SEQ / 64, BATCH);
    attn_kernel<<<ag, 128, ATTN_SMEM_BYTES>>>(out);
}

// round 6
// speedup vs baseline: 3.3340x; 1.0680x over previous
#include <cuda_runtime.h>
#include <cstdint>

#define BATCH 4
#define SEQ   4096
#define NEMB  1024
#define HD    128

// Scratch (device globals: allocation-free per harness rules)
__device__ float g_q [BATCH * SEQ * HD];   // pre-scaled, tf32-rounded
__device__ float g_k [BATCH * SEQ * HD];   // tf32-rounded
__device__ float g_vt[BATCH * HD * SEQ];   // transposed [b][h][t], tf32-rounded
__device__ float g_wth[3 * HD * NEMB];     // W^T hi  [which][n][k]
__device__ float g_wtl[3 * HD * NEMB];     // W^T lo

__device__ __forceinline__ float f2tf_f(float x) {
    uint32_t r;
    asm("cvt.rna.tf32.f32 %0, %1;" : "=r"(r) : "f"(x));
    return __uint_as_float(r);
}
__device__ __forceinline__ float ex2(float x) {
    float r;
    asm("ex2.approx.f32 %0, %1;" : "=f"(r) : "f"(x));
    return r;
}
__device__ __forceinline__ void mma8(float* d, const uint32_t* a, uint32_t b0, uint32_t b1) {
    asm volatile(
        "mma.sync.aligned.m16n8k8.row.col.f32.tf32.tf32.f32 "
        "{%0,%1,%2,%3}, {%4,%5,%6,%7}, {%8,%9}, {%0,%1,%2,%3};"
        : "+f"(d[0]), "+f"(d[1]), "+f"(d[2]), "+f"(d[3])
        : "r"(a[0]), "r"(a[1]), "r"(a[2]), "r"(a[3]), "r"(b0), "r"(b1));
}
__device__ __forceinline__ void ldsm4(uint32_t* r, uint32_t addr) {
    asm volatile("ldmatrix.sync.aligned.m8n8.x4.shared.b16 {%0,%1,%2,%3}, [%4];"
                 : "=r"(r[0]), "=r"(r[1]), "=r"(r[2]), "=r"(r[3]) : "r"(addr));
}
__device__ __forceinline__ uint32_t sptr(const void* p) {
    return (uint32_t)__cvta_generic_to_shared(p);
}

#define Q_SCALE (0.03125f * 1.44269504088896340736f)   // 1/sqrt(1024) * log2(e)

// ---------------------------------------------------------------------------
// prep: W^T hi/lo split, [which][n][k] layout
// ---------------------------------------------------------------------------
__global__ void prep_w(const float* __restrict__ Wq,
                       const float* __restrict__ Wk,
                       const float* __restrict__ Wv)
{
    int idx = blockIdx.x * 256 + threadIdx.x;          // 3*128*1024 total
    int which = idx >> 17;
    int r = idx & 131071;
    int n = r >> 10, k = r & 1023;
    const float* W = (which == 0) ? Wq : (which == 1) ? Wk : Wv;
    float v = W[(size_t)k * HD + n];
    float h = f2tf_f(v);
    g_wth[idx] = h;
    g_wtl[idx] = f2tf_f(v - h);
}

// ---------------------------------------------------------------------------
// QKV projection, 2-term split (A once-rounded, W hi+lo).
// Block 128x128, 8 warps (wm 0..3 x wn 0..1), BK=16, ldmatrix frags.
// ---------------------------------------------------------------------------
#define PJ_LD 20
#define PROJ_SMEM_FLOATS (3 * 128 * PJ_LD)
#define PROJ_SMEM_BYTES  (PROJ_SMEM_FLOATS * 4)

__global__ __launch_bounds__(256, 2) void proj_kernel(const float* __restrict__ x)
{
    extern __shared__ float psm[];
    float* As = psm;
    float* Bh = psm + 128 * PJ_LD;
    float* Bl = psm + 2 * 128 * PJ_LD;

    const int which = blockIdx.y;
    const float* __restrict__ Wh = g_wth + which * (HD * NEMB);
    const float* __restrict__ Wl = g_wtl + which * (HD * NEMB);

    const int m0   = blockIdx.x * 128;
    const int tid  = threadIdx.x;
    const int lane = tid & 31, wid = tid >> 5;
    const int wm = wid & 3, wn = wid >> 2;
    const int qr = lane >> 2, qc = lane & 3;

    const int arow  = (lane & 7) + 8 * ((lane >> 3) & 1);
    const int acsel = 4 * ((lane >> 4) & 1);
    const int brow  = lane & 7;
    const int bcsel = 4 * ((lane >> 3) & 3);

    const uint32_t As_u = sptr(As), Bh_u = sptr(Bh), Bl_u = sptr(Bl);

    float acc[2][8][4];
#pragma unroll
    for (int mt = 0; mt < 2; mt++)
#pragma unroll
        for (int nt = 0; nt < 8; nt++)
#pragma unroll
            for (int e = 0; e < 4; e++) acc[mt][nt][e] = 0.f;

    const int fr = tid >> 2, fc = (tid & 3) * 4;   // fill mapping (2 f4/thread/array)

#pragma unroll 1
    for (int k0 = 0; k0 < NEMB; k0 += 16) {
        // ---- fill ----
#pragma unroll
        for (int i = 0; i < 2; i++) {
            int r = fr + i * 64;
            float4 v = *reinterpret_cast<const float4*>(x + (size_t)(m0 + r) * NEMB + k0 + fc);
            v.x = f2tf_f(v.x); v.y = f2tf_f(v.y);
            v.z = f2tf_f(v.z); v.w = f2tf_f(v.w);
            *reinterpret_cast<float4*>(As + r * PJ_LD + fc) = v;
            *reinterpret_cast<float4*>(Bh + r * PJ_LD + fc) =
                *reinterpret_cast<const float4*>(Wh + (size_t)r * NEMB + k0 + fc);
            *reinterpret_cast<float4*>(Bl + r * PJ_LD + fc) =
                *reinterpret_cast<const float4*>(Wl + (size_t)r * NEMB + k0 + fc);
        }
        __syncthreads();

        // ---- frags + mma ----
        uint32_t a[2][2][4];
#pragma unroll
        for (int ks = 0; ks < 2; ks++)
#pragma unroll
            for (int mt = 0; mt < 2; mt++)
                ldsm4(a[ks][mt],
                      As_u + ((wm * 32 + mt * 16 + arow) * PJ_LD + ks * 8 + acsel) * 4);
#pragma unroll
        for (int nt = 0; nt < 8; nt++) {
            int n0 = wn * 64 + nt * 8;
            uint32_t boff = ((n0 + brow) * PJ_LD + bcsel) * 4;
            uint32_t bh[4], bl[4];
            ldsm4(bh, Bh_u + boff);
            ldsm4(bl, Bl_u + boff);
#pragma unroll
            for (int mt = 0; mt < 2; mt++) {
                mma8(acc[mt][nt], a[0][mt], bh[0], bh[1]);
                mma8(acc[mt][nt], a[1][mt], bh[2], bh[3]);
                mma8(acc[mt][nt], a[0][mt], bl[0], bl[1]);
                mma8(acc[mt][nt], a[1][mt], bl[2], bl[3]);
            }
        }
        __syncthreads();
    }

    // ---- epilogue: tf32-round outputs; q pre-scaled; v transposed ----
#pragma unroll
    for (int mt = 0; mt < 2; mt++)
#pragma unroll
        for (int nt = 0; nt < 8; nt++) {
            int row = m0 + wm * 32 + mt * 16 + qr;
            int col = wn * 64 + nt * 8 + 2 * qc;
            float v0 = acc[mt][nt][0], v1 = acc[mt][nt][1];
            float v2 = acc[mt][nt][2], v3 = acc[mt][nt][3];
            if (which == 0) { v0 *= Q_SCALE; v1 *= Q_SCALE; v2 *= Q_SCALE; v3 *= Q_SCALE; }
            v0 = f2tf_f(v0); v1 = f2tf_f(v1); v2 = f2tf_f(v2); v3 = f2tf_f(v3);
            if (which == 2) {
                int b = row >> 12, t = row & 4095;
                size_t base = (size_t)b * (HD * SEQ);
                g_vt[base + (size_t)col * SEQ + t]           = v0;
                g_vt[base + (size_t)(col + 1) * SEQ + t]     = v1;
                g_vt[base + (size_t)col * SEQ + t + 8]       = v2;
                g_vt[base + (size_t)(col + 1) * SEQ + t + 8] = v3;
            } else {
                float* outp = (which == 0) ? g_q : g_k;
                *reinterpret_cast<float2*>(outp + (size_t)row * HD + col) = make_float2(v0, v1);
                *reinterpret_cast<float2*>(outp + (size_t)(row + 8) * HD + col) = make_float2(v2, v3);
            }
        }
}

// ---------------------------------------------------------------------------
// Flash attention, causal, tf32 mma + ldmatrix. BM=BN=64, 4 warps x 16 rows.
// Smem: Qs[64][132] (aliased by per-warp Ps[16][68] after frag extraction),
//       Ks[64][132], Vt[128][68] (V transposed: row=h, col=t).
// ---------------------------------------------------------------------------
#define KS_LD 132
#define VT_LD 68
#define PS_LD 68
#define AK_OFF (64 * KS_LD)
#define AV_OFF (2 * 64 * KS_LD)
#define ATTN_SMEM_FLOATS (2 * 64 * KS_LD + HD * VT_LD)
#define ATTN_SMEM_BYTES  (ATTN_SMEM_FLOATS * 4)

__global__ __launch_bounds__(128, 2) void attn_kernel(float* __restrict__ out)
{
    extern __shared__ float sm[];
    float* Qs = sm;
    float* Ks = sm + AK_OFF;
    float* Vt = sm + AV_OFF;

    const int b  = blockIdx.y;
    const int bx = blockIdx.x;
    const int ib = (bx & 1) ? (SEQ / 64 - 1 - (bx >> 1)) : (bx >> 1);
    const int q0 = ib * 64;
    const int tid = threadIdx.x;
    const int lane = tid & 31, w = tid >> 5;
    const int qr = lane >> 2, qc = lane & 3;
    float* Ps = Qs + w * (16 * PS_LD);

    const int arow  = (lane & 7) + 8 * ((lane >> 3) & 1);
    const int acsel = 4 * ((lane >> 4) & 1);
    const int brow  = lane & 7;
    const int bcsel = 4 * ((lane >> 3) & 3);

    const uint32_t Ks_u = sptr(Ks), Vt_u = sptr(Vt), Ps_u = sptr(Ps);

    // ---- Q fill (already scaled + tf32), frag extraction via ldmatrix ----
    const float* __restrict__ qg = g_q + ((size_t)b * SEQ + q0) * HD;
#pragma unroll
    for (int i = 0; i < 16; i++) {
        int r = 16 * w + i;
        *reinterpret_cast<float4*>(Qs + r * KS_LD + lane * 4) =
            *reinterpret_cast<const float4*>(qg + (size_t)r * HD + lane * 4);
    }
    __syncwarp();
    uint32_t qa[16][4];
    {
        uint32_t qbase = sptr(Qs) + ((16 * w + arow) * KS_LD + acsel) * 4;
#pragma unroll
        for (int kt = 0; kt < 16; kt++) ldsm4(qa[kt], qbase + kt * 32);
    }

    float o[16][4];
#pragma unroll
    for (int nt = 0; nt < 16; nt++)
#pragma unroll
        for (int e = 0; e < 4; e++) o[nt][e] = 0.f;
    float m_lo = -1e30f, m_hi = -1e30f, l_lo = 0.f, l_hi = 0.f;

    const float* __restrict__ kg  = g_k  + (size_t)b * SEQ * HD;
    const float* __restrict__ vtg = g_vt + (size_t)b * HD * SEQ;

    const int kfr = tid >> 5, kfc = (tid & 31) * 4;   // K fill: 2 rows per i-step
    const int vfr = tid >> 4, vfc = (tid & 15) * 4;   // V fill

#pragma unroll 1
    for (int jb = 0; jb <= ib; jb++) {
        __syncthreads();   // frag extraction / prev iter reads complete
#pragma unroll
        for (int i = 0; i < 16; i++) {
            int r = kfr + i * 4;
            *reinterpret_cast<float4*>(Ks + r * KS_LD + kfc) =
                *reinterpret_cast<const float4*>(kg + ((size_t)jb * 64 + r) * HD + kfc);
            int h = vfr + i * 8;
            *reinterpret_cast<float4*>(Vt + h * VT_LD + vfc) =
                *reinterpret_cast<const float4*>(vtg + (size_t)h * SEQ + jb * 64 + vfc);
        }
        __syncthreads();

        // ---- S = Q K^T : 8 n-tiles x 8 kt-pairs ----
        float s[8][4];
#pragma unroll
        for (int nt = 0; nt < 8; nt++)
#pragma unroll
            for (int e = 0; e < 4; e++) s[nt][e] = 0.f;
#pragma unroll
        for (int nt = 0; nt < 8; nt++) {
            uint32_t kb_base = Ks_u + ((nt * 8 + brow) * KS_LD + bcsel) * 4;
#pragma unroll
            for (int tp = 0; tp < 8; tp++) {
                uint32_t kb[4];
                ldsm4(kb, kb_base + tp * 64);
                mma8(s[nt], qa[2 * tp],     kb[0], kb[1]);
                mma8(s[nt], qa[2 * tp + 1], kb[2], kb[3]);
            }
        }

        // ---- causal mask (diagonal block) ----
        if (jb == ib) {
            int r_lo = 16 * w + qr, r_hi = r_lo + 8;
#pragma unroll
            for (int nt = 0; nt < 8; nt++) {
                int c = nt * 8 + 2 * qc;
                if (c     > r_lo) s[nt][0] = -1e30f;
                if (c + 1 > r_lo) s[nt][1] = -1e30f;
                if (c     > r_hi) s[nt][2] = -1e30f;
                if (c + 1 > r_hi) s[nt][3] = -1e30f;
            }
        }

        // ---- online softmax (exp2 domain; quad reduce) ----
        float mx_lo = -1e30f, mx_hi = -1e30f;
#pragma unroll
        for (int nt = 0; nt < 8; nt++) {
            mx_lo = fmaxf(mx_lo, fmaxf(s[nt][0], s[nt][1]));
            mx_hi = fmaxf(mx_hi, fmaxf(s[nt][2], s[nt][3]));
        }
#pragma unroll
        for (int d = 1; d <= 2; d <<= 1) {
            mx_lo = fmaxf(mx_lo, __shfl_xor_sync(0xffffffffu, mx_lo, d));
            mx_hi = fmaxf(mx_hi, __shfl_xor_sync(0xffffffffu, mx_hi, d));
        }
        float mn_lo = fmaxf(m_lo, mx_lo), mn_hi = fmaxf(m_hi, mx_hi);
        float al_lo = ex2(m_lo - mn_lo),  al_hi = ex2(m_hi - mn_hi);
        m_lo = mn_lo; m_hi = mn_hi;
        float ls_lo = 0.f, ls_hi = 0.f;
#pragma unroll
        for (int nt = 0; nt < 8; nt++) {
            s[nt][0] = ex2(s[nt][0] - mn_lo);
            s[nt][1] = ex2(s[nt][1] - mn_lo);
            s[nt][2] = ex2(s[nt][2] - mn_hi);
            s[nt][3] = ex2(s[nt][3] - mn_hi);
            ls_lo += s[nt][0] + s[nt][1];
            ls_hi += s[nt][2] + s[nt][3];
        }
#pragma unroll
        for (int d = 1; d <= 2; d <<= 1) {
            ls_lo += __shfl_xor_sync(0xffffffffu, ls_lo, d);
            ls_hi += __shfl_xor_sync(0xffffffffu, ls_hi, d);
        }
        l_lo = l_lo * al_lo + ls_lo;
        l_hi = l_hi * al_hi + ls_hi;
#pragma unroll
        for (int nt = 0; nt < 16; nt++) {
            o[nt][0] *= al_lo; o[nt][1] *= al_lo;
            o[nt][2] *= al_hi; o[nt][3] *= al_hi;
        }

        // ---- P -> per-warp smem (tf32), PV via ldmatrix ----
#pragma unroll
        for (int nt = 0; nt < 8; nt++) {
            *reinterpret_cast<float2*>(Ps + qr * PS_LD + nt * 8 + 2 * qc) =
                make_float2(f2tf_f(s[nt][0]), f2tf_f(s[nt][1]));
            *reinterpret_cast<float2*>(Ps + (qr + 8) * PS_LD + nt * 8 + 2 * qc) =
                make_float2(f2tf_f(s[nt][2]), f2tf_f(s[nt][3]));
        }
        __syncwarp();

        uint32_t pa_base = Ps_u + (arow * PS_LD + acsel) * 4;
#pragma unroll
        for (int tp = 0; tp < 4; tp++) {
            uint32_t pa0[4], pa1[4];
            ldsm4(pa0, pa_base + (2 * tp) * 32);
            ldsm4(pa1, pa_base + (2 * tp + 1) * 32);
#pragma unroll
            for (int nt = 0; nt < 16; nt++) {
                uint32_t vb[4];
                ldsm4(vb, Vt_u + ((nt * 8 + brow) * VT_LD + tp * 16 + bcsel) * 4);
                mma8(o[nt], pa0, vb[0], vb[1]);
                mma8(o[nt], pa1, vb[2], vb[3]);
            }
        }
    }

    // ---- epilogue ----
    float inv_lo = 1.f / l_lo, inv_hi = 1.f / l_hi;
    float* __restrict__ og = out + ((size_t)b * SEQ + q0) * HD;
    int r_lo = 16 * w + qr;
#pragma unroll
    for (int nt = 0; nt < 16; nt++) {
        int col = nt * 8 + 2 * qc;
        *reinterpret_cast<float2*>(og + (size_t)r_lo * HD + col) =
            make_float2(o[nt][0] * inv_lo, o[nt][1] * inv_lo);
        *reinterpret_cast<float2*>(og + (size_t)(r_lo + 8) * HD + col) =
            make_float2(o[nt][2] * inv_hi, o[nt][3] * inv_hi);
    }
}

// ---------------------------------------------------------------------------
extern "C" void kernel_launch(void* const* d_in, const int* in_sizes, int n_in,
                              void* d_out, int out_size)
{
    const float* x  = (const float*)d_in[0];
    const float* Wq = (const float*)d_in[1];
    const float* Wk = (const float*)d_in[2];
    const float* Wv = (const float*)d_in[3];
    float* out = (float*)d_out;

    cudaFuncSetAttribute(proj_kernel, cudaFuncAttributeMaxDynamicSharedMemorySize,
                         PROJ_SMEM_BYTES);
    cudaFuncSetAttribute(attn_kernel, cudaFuncAttributeMaxDynamicSharedMemorySize,
                         ATTN_SMEM_BYTES);

    prep_w<<<(3 * HD * NEMB) / 256, 256>>>(Wq, Wk, Wv);

    dim3 pg(BATCH * SEQ / 128, 3);
    proj_kernel<<<pg, 256, PROJ_SMEM_BYTES>>>(x);

    dim3 ag(SEQ / 64, BATCH);
    attn_kernel<<<ag, 128, ATTN_SMEM_BYTES>>>(out);
}

// round 10
// speedup vs baseline: 6.8398x; 2.0515x over previous
#include <cuda_runtime.h>
#include <cuda_fp16.h>
#include <cstdint>

#define BATCH 4
#define SEQ   4096
#define NEMB  1024
#define HD    128
#define Q_SCALE (0.03125f * 1.44269504088896340736f)   // 1/sqrt(1024) * log2(e)

// Scratch (device globals: allocation-free per harness rules)
__device__ __half g_qh [BATCH * SEQ * HD];    // q, pre-scaled, fp16
__device__ __half g_kh [BATCH * SEQ * HD];    // k, fp16
__device__ __half g_vth[BATCH * HD * SEQ];    // v transposed [b][h][t], fp16
__device__ __half g_xh [BATCH * SEQ * NEMB];  // x rounded to fp16
__device__ __half g_wth[3 * HD * NEMB];       // W^T hi fp16 [which][n][k]
__device__ __half g_wtl[3 * HD * NEMB];       // W^T lo fp16

__device__ __forceinline__ float ex2(float x) {
    float r; asm("ex2.approx.f32 %0, %1;" : "=f"(r) : "f"(x)); return r;
}
__device__ __forceinline__ uint32_t sptr(const void* p) {
    return (uint32_t)__cvta_generic_to_shared(p);
}
__device__ __forceinline__ void mma16(float* d, const uint32_t* a, uint32_t b0, uint32_t b1) {
    asm volatile(
        "mma.sync.aligned.m16n8k16.row.col.f32.f16.f16.f32 "
        "{%0,%1,%2,%3}, {%4,%5,%6,%7}, {%8,%9}, {%0,%1,%2,%3};"
        : "+f"(d[0]), "+f"(d[1]), "+f"(d[2]), "+f"(d[3])
        : "r"(a[0]), "r"(a[1]), "r"(a[2]), "r"(a[3]), "r"(b0), "r"(b1));
}
__device__ __forceinline__ void ldsm4(uint32_t* r, uint32_t a) {
    asm volatile("ldmatrix.sync.aligned.m8n8.x4.shared.b16 {%0,%1,%2,%3}, [%4];"
                 : "=r"(r[0]), "=r"(r[1]), "=r"(r[2]), "=r"(r[3]) : "r"(a));
}
__device__ __forceinline__ void cpa16(uint32_t dst, const void* src) {
    asm volatile("cp.async.cg.shared.global [%0], [%1], 16;" :: "r"(dst), "l"(src));
}
#define CP_COMMIT() asm volatile("cp.async.commit_group;" ::: "memory")
#define CP_WAIT1()  asm volatile("cp.async.wait_group 1;" ::: "memory")
#define CP_WAIT0()  asm volatile("cp.async.wait_group 0;" ::: "memory")

// ---------------------------------------------------------------------------
// prep kernels
// ---------------------------------------------------------------------------
__global__ void prep_w(const float* __restrict__ Wq,
                       const float* __restrict__ Wk,
                       const float* __restrict__ Wv)
{
    int idx = blockIdx.x * 256 + threadIdx.x;      // 3*128*1024
    int which = idx >> 17;
    int r = idx & 131071;
    int n = r >> 10, k = r & 1023;
    const float* W = (which == 0) ? Wq : (which == 1) ? Wk : Wv;
    float v = W[(size_t)k * HD + n];
    __half h = __float2half_rn(v);
    g_wth[idx] = h;
    g_wtl[idx] = __float2half_rn(v - __half2float(h));
}

__global__ void prep_x(const float* __restrict__ x)
{
    size_t i = ((size_t)blockIdx.x * 256 + threadIdx.x) * 4;
    float4 v = *reinterpret_cast<const float4*>(x + i);
    *reinterpret_cast<__half2*>(g_xh + i)     = __floats2half2_rn(v.x, v.y);
    *reinterpret_cast<__half2*>(g_xh + i + 2) = __floats2half2_rn(v.z, v.w);
}

// ---------------------------------------------------------------------------
// QKV projection: fp16 mma, 2-term W split, 3-stage cp.async pipeline.
// CTA tile 128x128, 8 warps (4 wm x 2 wn), BK=32 per stage.
// ---------------------------------------------------------------------------
#define NSTG   3
#define PJ_LDH 40                               // halves per row (pad 8)
#define PJ_SB  (128 * PJ_LDH * 2)               // 10240 B / array / stage
#define PJ_A(s)  ((s) * PJ_SB)
#define PJ_BH(s) ((NSTG + (s)) * PJ_SB)
#define PJ_BL(s) ((2 * NSTG + (s)) * PJ_SB)
#define PROJ_SMEM (3 * NSTG * PJ_SB)            // 92160 B

__device__ __forceinline__ void proj_fill(char* smem, int s, int c, int m0, int tid,
                                          const __half* Wh, const __half* Wl)
{
    const int k0 = c * 32;
    const uint32_t sb = sptr(smem);
#pragma unroll
    for (int i = 0; i < 2; i++) {
        int q = tid + i * 256;                  // 512 chunks per array
        int r = q >> 2, c16 = q & 3;
        uint32_t d = (uint32_t)(r * (PJ_LDH * 2) + c16 * 16);
        cpa16(sb + PJ_A(s)  + d, g_xh + (size_t)(m0 + r) * NEMB + k0 + c16 * 8);
        cpa16(sb + PJ_BH(s) + d, Wh + (size_t)r * NEMB + k0 + c16 * 8);
        cpa16(sb + PJ_BL(s) + d, Wl + (size_t)r * NEMB + k0 + c16 * 8);
    }
}

__global__ __launch_bounds__(256, 2) void proj_kernel()
{
    extern __shared__ char psm[];
    const uint32_t sb = sptr(psm);

    const int which = blockIdx.y;
    const __half* __restrict__ Wh = g_wth + which * (HD * NEMB);
    const __half* __restrict__ Wl = g_wtl + which * (HD * NEMB);

    const int m0   = blockIdx.x * 128;
    const int tid  = threadIdx.x;
    const int lane = tid & 31, wid = tid >> 5;
    const int wm = wid & 3, wn = wid >> 2;
    const int g = lane >> 2, t = lane & 3;
    const int arow = (lane & 7) + 8 * ((lane >> 3) & 1);
    const int asec = lane >> 4;                 // col += 8*asec
    const int brow = lane & 7;
    const int bsec = lane >> 3;                 // col = 8*bsec

    float acc[2][8][4];
#pragma unroll
    for (int mt = 0; mt < 2; mt++)
#pragma unroll
        for (int nt = 0; nt < 8; nt++)
#pragma unroll
            for (int e = 0; e < 4; e++) acc[mt][nt][e] = 0.f;

    proj_fill(psm, 0, 0, m0, tid, Wh, Wl); CP_COMMIT();
    proj_fill(psm, 1, 1, m0, tid, Wh, Wl); CP_COMMIT();

#pragma unroll 1
    for (int c = 0; c < 32; c++) {
        if (c < 31) CP_WAIT1(); else CP_WAIT0();
        __syncthreads();
        if (c + 2 < 32) { proj_fill(psm, (c + 2) % 3, c + 2, m0, tid, Wh, Wl); CP_COMMIT(); }

        const int s = c % 3;
        uint32_t a[2][2][4];
#pragma unroll
        for (int mt = 0; mt < 2; mt++)
#pragma unroll
            for (int ks = 0; ks < 2; ks++)
                ldsm4(a[mt][ks], sb + PJ_A(s) +
                      ((wm * 32 + mt * 16 + arow) * PJ_LDH + ks * 16 + 8 * asec) * 2);
#pragma unroll
        for (int nt = 0; nt < 8; nt++) {
            int n0 = wn * 64 + nt * 8;
            uint32_t boff = (uint32_t)((n0 + brow) * PJ_LDH + 8 * bsec) * 2;
            uint32_t bh[4], bl[4];
            ldsm4(bh, sb + PJ_BH(s) + boff);
            ldsm4(bl, sb + PJ_BL(s) + boff);
#pragma unroll
            for (int mt = 0; mt < 2; mt++) {
                mma16(acc[mt][nt], a[mt][0], bh[0], bh[1]);
                mma16(acc[mt][nt], a[mt][1], bh[2], bh[3]);
                mma16(acc[mt][nt], a[mt][0], bl[0], bl[1]);
                mma16(acc[mt][nt], a[mt][1], bl[2], bl[3]);
            }
        }
    }

    // ---- epilogue ----
#pragma unroll
    for (int mt = 0; mt < 2; mt++)
#pragma unroll
        for (int nt = 0; nt < 8; nt++) {
            int row = m0 + wm * 32 + mt * 16 + g;
            int col = wn * 64 + nt * 8 + 2 * t;
            float v0 = acc[mt][nt][0], v1 = acc[mt][nt][1];
            float v2 = acc[mt][nt][2], v3 = acc[mt][nt][3];
            if (which == 0) { v0 *= Q_SCALE; v1 *= Q_SCALE; v2 *= Q_SCALE; v3 *= Q_SCALE; }
            if (which == 2) {
                int bb = row >> 12, tt = row & 4095;
                __half* vt = g_vth + (size_t)bb * (HD * SEQ) + tt;
                vt[(size_t)col * SEQ]           = __float2half_rn(v0);
                vt[(size_t)(col + 1) * SEQ]     = __float2half_rn(v1);
                vt[(size_t)col * SEQ + 8]       = __float2half_rn(v2);
                vt[(size_t)(col + 1) * SEQ + 8] = __float2half_rn(v3);
            } else {
                __half* outp = (which == 0) ? g_qh : g_kh;
                *reinterpret_cast<__half2*>(outp + (size_t)row * HD + col) =
                    __floats2half2_rn(v0, v1);
                *reinterpret_cast<__half2*>(outp + (size_t)(row + 8) * HD + col) =
                    __floats2half2_rn(v2, v3);
            }
        }
}

// ---------------------------------------------------------------------------
// Flash attention, causal, fp16 mma + ldmatrix + cp.async double buffering.
// BM=BN=64, 4 warps x 16 rows. Smem: K[2][64][136]h, Vt[2][128][72]h,
// Ps[4][16][72]h; Q staged in K buf 0. 80896 B -> 2 CTAs/SM.
// ---------------------------------------------------------------------------
#define K_LDH 136
#define V_LDH 72
#define P_LDH 72
#define AK_STRIDE (64 * K_LDH * 2)              // 17408
#define AV_STRIDE (128 * V_LDH * 2)             // 18432
#define A_KOFF 0
#define A_VOFF (2 * AK_STRIDE)                  // 34816
#define A_POFF (A_VOFF + 2 * AV_STRIDE)         // 71680
#define ATTN_SMEM (A_POFF + 4 * 16 * P_LDH * 2) // 80896

__device__ __forceinline__ void attn_issue(char* smem, int buf, int jb, int tid,
                                           const __half* kg, const __half* vtg)
{
    const uint32_t sb = sptr(smem);
#pragma unroll
    for (int i = 0; i < 8; i++) {
        int q = tid + i * 128;
        int r = q >> 4, c16 = q & 15;           // K: 64 rows x 16 chunks
        cpa16(sb + A_KOFF + buf * AK_STRIDE + r * (K_LDH * 2) + c16 * 16,
              kg + (size_t)(jb * 64 + r) * HD + c16 * 8);
        int h = q >> 3, d16 = q & 7;            // V: 128 rows x 8 chunks
        cpa16(sb + A_VOFF + buf * AV_STRIDE + h * (V_LDH * 2) + d16 * 16,
              vtg + (size_t)h * SEQ + jb * 64 + d16 * 8);
    }
}

__global__ __launch_bounds__(128, 2) void attn_kernel(float* __restrict__ out)
{
    extern __shared__ char smc[];
    const uint32_t sb = sptr(smc);

    const int b  = blockIdx.y;
    const int bx = blockIdx.x;
    const int ib = (bx & 1) ? (SEQ / 64 - 1 - (bx >> 1)) : (bx >> 1);
    const int q0 = ib * 64;
    const int tid = threadIdx.x;
    const int lane = tid & 31, w = tid >> 5;
    const int g = lane >> 2, t = lane & 3;
    const int arow = (lane & 7) + 8 * ((lane >> 3) & 1);
    const int asec = lane >> 4;
    const int brow = lane & 7;
    const int bsec = lane >> 3;

    const __half* __restrict__ kg  = g_kh  + (size_t)b * SEQ * HD;
    const __half* __restrict__ vtg = g_vth + (size_t)b * HD * SEQ;

    // ---- stage Q into K buf 0 (warp-private rows), extract fp16 A-frags ----
    const __half* __restrict__ qg = g_qh + ((size_t)b * SEQ + q0) * HD;
#pragma unroll
    for (int i = 0; i < 8; i++) {
        int q = lane + i * 32;
        int r = q >> 4, c16 = q & 15;
        *reinterpret_cast<uint4*>(smc + A_KOFF + (16 * w + r) * (K_LDH * 2) + c16 * 16) =
            *reinterpret_cast<const uint4*>(qg + (size_t)(16 * w + r) * HD + c16 * 8);
    }
    __syncwarp();
    uint32_t qa[8][4];
    {
        uint32_t qb = sb + A_KOFF + ((16 * w + arow) * K_LDH + 8 * asec) * 2;
#pragma unroll
        for (int ks = 0; ks < 8; ks++) ldsm4(qa[ks], qb + ks * 32);
    }
    __syncthreads();
    attn_issue(smc, 0, 0, tid, kg, vtg); CP_COMMIT();

    float o[16][4];
#pragma unroll
    for (int nt = 0; nt < 16; nt++)
#pragma unroll
        for (int e = 0; e < 4; e++) o[nt][e] = 0.f;
    float m_lo = -1e30f, m_hi = -1e30f, l_lo = 0.f, l_hi = 0.f;

#pragma unroll 1
    for (int jb = 0; jb <= ib; jb++) {
        const int buf = jb & 1;
        if (jb < ib) {
            attn_issue(smc, buf ^ 1, jb + 1, tid, kg, vtg); CP_COMMIT(); CP_WAIT1();
        } else {
            CP_WAIT0();
        }
        __syncthreads();

        // ---- S = Q K^T : 8 n-tiles x 8 k16-steps ----
        float s[8][4];
#pragma unroll
        for (int nt = 0; nt < 8; nt++)
#pragma unroll
            for (int e = 0; e < 4; e++) s[nt][e] = 0.f;
#pragma unroll
        for (int nt = 0; nt < 8; nt++) {
            uint32_t ka = sb + A_KOFF + buf * AK_STRIDE +
                          ((nt * 8 + brow) * K_LDH + 8 * bsec) * 2;
#pragma unroll
            for (int kc = 0; kc < 4; kc++) {
                uint32_t kb[4];
                ldsm4(kb, ka + kc * 64);
                mma16(s[nt], qa[2 * kc],     kb[0], kb[1]);
                mma16(s[nt], qa[2 * kc + 1], kb[2], kb[3]);
            }
        }

        // ---- causal mask ----
        if (jb == ib) {
            int r_lo = 16 * w + g, r_hi = r_lo + 8;
#pragma unroll
            for (int nt = 0; nt < 8; nt++) {
                int cc = nt * 8 + 2 * t;
                if (cc     > r_lo) s[nt][0] = -1e30f;
                if (cc + 1 > r_lo) s[nt][1] = -1e30f;
                if (cc     > r_hi) s[nt][2] = -1e30f;
                if (cc + 1 > r_hi) s[nt][3] = -1e30f;
            }
        }

        // ---- online softmax (exp2 domain, quad reduce) ----
        float mx_lo = -1e30f, mx_hi = -1e30f;
#pragma unroll
        for (int nt = 0; nt < 8; nt++) {
            mx_lo = fmaxf(mx_lo, fmaxf(s[nt][0], s[nt][1]));
            mx_hi = fmaxf(mx_hi, fmaxf(s[nt][2], s[nt][3]));
        }
#pragma unroll
        for (int d = 1; d <= 2; d <<= 1) {
            mx_lo = fmaxf(mx_lo, __shfl_xor_sync(0xffffffffu, mx_lo, d));
            mx_hi = fmaxf(mx_hi, __shfl_xor_sync(0xffffffffu, mx_hi, d));
        }
        float mn_lo = fmaxf(m_lo, mx_lo), mn_hi = fmaxf(m_hi, mx_hi);
        float al_lo = ex2(m_lo - mn_lo),  al_hi = ex2(m_hi - mn_hi);
        m_lo = mn_lo; m_hi = mn_hi;
        float ls_lo = 0.f, ls_hi = 0.f;
#pragma unroll
        for (int nt = 0; nt < 8; nt++) {
            s[nt][0] = ex2(s[nt][0] - mn_lo);
            s[nt][1] = ex2(s[nt][1] - mn_lo);
            s[nt][2] = ex2(s[nt][2] - mn_hi);
            s[nt][3] = ex2(s[nt][3] - mn_hi);
            ls_lo += s[nt][0] + s[nt][1];
            ls_hi += s[nt][2] + s[nt][3];
        }
#pragma unroll
        for (int d = 1; d <= 2; d <<= 1) {
            ls_lo += __shfl_xor_sync(0xffffffffu, ls_lo, d);
            ls_hi += __shfl_xor_sync(0xffffffffu, ls_hi, d);
        }
        l_lo = l_lo * al_lo + ls_lo;
        l_hi = l_hi * al_hi + ls_hi;
#pragma unroll
        for (int nt = 0; nt < 16; nt++) {
            o[nt][0] *= al_lo; o[nt][1] *= al_lo;
            o[nt][2] *= al_hi; o[nt][3] *= al_hi;
        }

        // ---- P (fp16) -> per-warp smem, PV ----
        __half* Psh = reinterpret_cast<__half*>(smc + A_POFF) + w * (16 * P_LDH);
#pragma unroll
        for (int nt = 0; nt < 8; nt++) {
            *reinterpret_cast<__half2*>(Psh + g * P_LDH + nt * 8 + 2 * t) =
                __floats2half2_rn(s[nt][0], s[nt][1]);
            *reinterpret_cast<__half2*>(Psh + (g + 8) * P_LDH + nt * 8 + 2 * t) =
                __floats2half2_rn(s[nt][2], s[nt][3]);
        }
        __syncwarp();

        uint32_t pu = sptr(Psh) + (arow * P_LDH + 8 * asec) * 2;
        uint32_t pa[4][4];
#pragma unroll
        for (int ks = 0; ks < 4; ks++) ldsm4(pa[ks], pu + ks * 32);
#pragma unroll
        for (int nt = 0; nt < 16; nt++) {
            uint32_t va = sb + A_VOFF + buf * AV_STRIDE +
                          ((nt * 8 + brow) * V_LDH + 8 * bsec) * 2;
#pragma unroll
            for (int kc = 0; kc < 2; kc++) {
                uint32_t vb[4];
                ldsm4(vb, va + kc * 64);
                mma16(o[nt], pa[2 * kc],     vb[0], vb[1]);
                mma16(o[nt], pa[2 * kc + 1], vb[2], vb[3]);
            }
        }
        __syncthreads();
    }

    // ---- epilogue ----
    float inv_lo = 1.f / l_lo, inv_hi = 1.f / l_hi;
    float* __restrict__ og = out + ((size_t)b * SEQ + q0) * HD;
    int r_lo = 16 * w + g;
#pragma unroll
    for (int nt = 0; nt < 16; nt++) {
        int col = nt * 8 + 2 * t;
        *reinterpret_cast<float2*>(og + (size_t)r_lo * HD + col) =
            make_float2(o[nt][0] * inv_lo, o[nt][1] * inv_lo);
        *reinterpret_cast<float2*>(og + (size_t)(r_lo + 8) * HD + col) =
            make_float2(o[nt][2] * inv_hi, o[nt][3] * inv_hi);
    }
}

// ---------------------------------------------------------------------------
extern "C" void kernel_launch(void* const* d_in, const int* in_sizes, int n_in,
                              void* d_out, int out_size)
{
    const float* x  = (const float*)d_in[0];
    const float* Wq = (const float*)d_in[1];
    const float* Wk = (const float*)d_in[2];
    const float* Wv = (const float*)d_in[3];
    float* out = (float*)d_out;

    cudaFuncSetAttribute(proj_kernel, cudaFuncAttributeMaxDynamicSharedMemorySize,
                         PROJ_SMEM);
    cudaFuncSetAttribute(attn_kernel, cudaFuncAttributeMaxDynamicSharedMemorySize,
                         ATTN_SMEM);

    prep_w<<<(3 * HD * NEMB) / 256, 256>>>(Wq, Wk, Wv);
    prep_x<<<(BATCH * SEQ * NEMB) / 1024, 256>>>(x);

    dim3 pg(BATCH * SEQ / 128, 3);
    proj_kernel<<<pg, 256, PROJ_SMEM>>>();

    dim3 ag(SEQ / 64, BATCH);
    attn_kernel<<<ag, 128, ATTN_SMEM>>>(out);
}